// round 12
// baseline (speedup 1.0000x reference)
#include <cuda_runtime.h>
#include <cuda_bf16.h>
#include <cuda_fp16.h>
#include <math.h>
#include <stdint.h>

#define BATCH 2
#define SEQ   4096
#define DMODEL 512
#define NHEAD 8
#define HDIM  64
#define MROWS (BATCH*SEQ)
#define MAXREL 2

typedef unsigned long long ull;

// scratch
__device__ float g_A[MROWS * DMODEL];
__device__ unsigned short g_Qh[MROWS * DMODEL];   // fp16
__device__ unsigned short g_Kh[MROWS * DMODEL];   // fp16
__device__ unsigned short g_Vh[MROWS * DMODEL];   // fp16

// split (a,b) into bf16 hi-pair + lo-pair words (GEMM internals): h={lo=a,hi=b}
__device__ __forceinline__ void split2(float a, float b, uint32_t& h, uint32_t& l) {
    asm("cvt.rn.bf16x2.f32 %0, %1, %2;" : "=r"(h) : "f"(b), "f"(a));
    float ha = __uint_as_float(h << 16);
    float hb = __uint_as_float(h & 0xffff0000u);
    float ra = a - ha, rb = b - hb;
    asm("cvt.rn.bf16x2.f32 %0, %1, %2;" : "=r"(l) : "f"(rb), "f"(ra));
}
// pack (a,b) -> fp16x2 {lo=a, hi=b}
__device__ __forceinline__ uint32_t pkhf2(float a, float b) {
    uint32_t h;
    asm("cvt.rn.f16x2.f32 %0, %1, %2;" : "=r"(h) : "f"(b), "f"(a));
    return h;
}

static __device__ __forceinline__ uint32_t smem_u32(const void* p) {
    uint32_t a;
    asm("{ .reg .u64 t; cvta.to.shared.u64 t, %1; cvt.u32.u64 %0, t; }" : "=r"(a) : "l"(p));
    return a;
}
__device__ __forceinline__ void ldsm4(uint32_t* r, uint32_t addr) {
    asm volatile("ldmatrix.sync.aligned.m8n8.x4.shared.b16 {%0,%1,%2,%3}, [%4];"
                 : "=r"(r[0]), "=r"(r[1]), "=r"(r[2]), "=r"(r[3]) : "r"(addr));
}
__device__ __forceinline__ void ldsm4t(uint32_t* r, uint32_t addr) {
    asm volatile("ldmatrix.sync.aligned.m8n8.x4.trans.shared.b16 {%0,%1,%2,%3}, [%4];"
                 : "=r"(r[0]), "=r"(r[1]), "=r"(r[2]), "=r"(r[3]) : "r"(addr));
}
// bf16 mma (GEMM)
__device__ __forceinline__ void mmabf16(float* c, const uint32_t* a, uint32_t b0, uint32_t b1) {
    asm volatile("mma.sync.aligned.m16n8k16.row.col.f32.bf16.bf16.f32 "
                 "{%0,%1,%2,%3}, {%4,%5,%6,%7}, {%8,%9}, {%0,%1,%2,%3};"
                 : "+f"(c[0]), "+f"(c[1]), "+f"(c[2]), "+f"(c[3])
                 : "r"(a[0]), "r"(a[1]), "r"(a[2]), "r"(a[3]), "r"(b0), "r"(b1));
}
// fp16 mma (attention)
__device__ __forceinline__ void mmaf16(float* c, const uint32_t* a, uint32_t b0, uint32_t b1) {
    asm volatile("mma.sync.aligned.m16n8k16.row.col.f32.f16.f16.f32 "
                 "{%0,%1,%2,%3}, {%4,%5,%6,%7}, {%8,%9}, {%0,%1,%2,%3};"
                 : "+f"(c[0]), "+f"(c[1]), "+f"(c[2]), "+f"(c[3])
                 : "r"(a[0]), "r"(a[1]), "r"(a[2]), "r"(a[3]), "r"(b0), "r"(b1));
}
__device__ __forceinline__ void cpa16(uint32_t d, const void* s) {
    asm volatile("cp.async.cg.shared.global [%0], [%1], 16;" :: "r"(d), "l"(s));
}
#define CP_COMMIT() asm volatile("cp.async.commit_group;" ::: "memory")
#define CP_WAIT1()  asm volatile("cp.async.wait_group 1;" ::: "memory")

#define SW128(o) ((o) ^ (((o) >> 3) & 0x70))
#define SW64(o)  ((o) ^ (((o) >> 3) & 0x30))

// ---------------------------------------------------------------------------
// Tensor-core GEMM, 3-term bf16 split internals (exact path) — unchanged.
// mode 0: fp32 out.  mode 1: fp16 out, value = scale*(acc+bias).
// ---------------------------------------------------------------------------
__global__ __launch_bounds__(256, 2) void gemm_bf16(const float* __restrict__ X,
                                                    const float* __restrict__ W,
                                                    const float* __restrict__ bias,
                                                    float* __restrict__ Cf,
                                                    unsigned short* __restrict__ Ch,
                                                    float scale, int mode)
{
    __shared__ char smp[32768];
    const uint32_t sb = smem_u32(smp);
#define GXH 0
#define GXL 8192
#define GWH 16384
#define GWL 24576

    const int tid = threadIdx.x;
    const int w = tid >> 5;
    const int lane = tid & 31;
    const int m0 = blockIdx.y * 128, n0 = blockIdx.x * 128;

    const int row = tid >> 1;
    const int half = tid & 1;

    const float* Xg = X + (size_t)(m0 + row) * DMODEL + half * 16;
    const float* Wg = W + (size_t)(n0 + row) * DMODEL + half * 16;

    const uint32_t base_a = (uint32_t)((16 * w + (lane & 15)) * 64 + (lane >> 4) * 16);
    const uint32_t base_b = (uint32_t)(((lane & 7) + ((lane & 16) >> 1)) * 64 + ((lane >> 3) & 1) * 16);

    float cs[16][4];
#pragma unroll
    for (int i = 0; i < 16; i++)
#pragma unroll
        for (int j = 0; j < 4; j++) cs[i][j] = 0.f;

    float4 xr[4], wr[4];
#pragma unroll
    for (int i = 0; i < 4; i++) {
        xr[i] = *(const float4*)(Xg + i * 4);
        wr[i] = *(const float4*)(Wg + i * 4);
    }

    for (int ks = 0; ks < DMODEL / 32; ks++) {
        __syncthreads();
#pragma unroll
        for (int i = 0; i < 4; i++) {
            uint32_t h0, l0, h1, l1;
            split2(xr[i].x, xr[i].y, h0, l0);
            split2(xr[i].z, xr[i].w, h1, l1);
            const uint32_t off = SW64((uint32_t)(row * 64 + half * 32 + i * 8));
            *(uint2*)(smp + GXH + off) = make_uint2(h0, h1);
            *(uint2*)(smp + GXL + off) = make_uint2(l0, l1);
            split2(wr[i].x, wr[i].y, h0, l0);
            split2(wr[i].z, wr[i].w, h1, l1);
            *(uint2*)(smp + GWH + off) = make_uint2(h0, h1);
            *(uint2*)(smp + GWL + off) = make_uint2(l0, l1);
        }
        __syncthreads();

        if (ks + 1 < DMODEL / 32) {
            const int k1 = (ks + 1) * 32;
#pragma unroll
            for (int i = 0; i < 4; i++) {
                xr[i] = *(const float4*)(Xg + k1 + i * 4);
                wr[i] = *(const float4*)(Wg + k1 + i * 4);
            }
        }

#pragma unroll
        for (int c = 0; c < 2; c++) {
            uint32_t ah[4], al[4];
            const uint32_t aoff = SW64(base_a + 32u * c);
            ldsm4(ah, sb + GXH + aoff);
            ldsm4(al, sb + GXL + aoff);
#pragma unroll
            for (int j2 = 0; j2 < 8; j2++) {
                uint32_t bh[4], bl[4];
                const uint32_t boff = SW64(base_b + 1024u * j2 + 32u * c);
                ldsm4(bh, sb + GWH + boff);
                ldsm4(bl, sb + GWL + boff);
                mmabf16(cs[2 * j2], ah, bh[0], bh[1]);
                mmabf16(cs[2 * j2], ah, bl[0], bl[1]);
                mmabf16(cs[2 * j2], al, bh[0], bh[1]);
                mmabf16(cs[2 * j2 + 1], ah, bh[2], bh[3]);
                mmabf16(cs[2 * j2 + 1], ah, bl[2], bl[3]);
                mmabf16(cs[2 * j2 + 1], al, bh[2], bh[3]);
            }
        }
    }

    const int rr = m0 + 16 * w + (lane >> 2);
    const int cc = 2 * (lane & 3);
    if (mode == 0) {
#pragma unroll
        for (int t = 0; t < 16; t++) {
            const int col = n0 + 8 * t + cc;
            const float2 bv = *(const float2*)(bias + col);
            float* C0 = Cf + (size_t)rr * DMODEL + col;
            *(float2*)C0 = make_float2(cs[t][0] + bv.x, cs[t][1] + bv.y);
            *(float2*)(C0 + 8 * DMODEL) = make_float2(cs[t][2] + bv.x, cs[t][3] + bv.y);
        }
    } else {
#pragma unroll
        for (int t = 0; t < 16; t++) {
            const int col = n0 + 8 * t + cc;
            const float2 bv = *(const float2*)(bias + col);
            *(uint32_t*)(Ch + (size_t)rr * DMODEL + col) =
                pkhf2(scale * (cs[t][0] + bv.x), scale * (cs[t][1] + bv.y));
            *(uint32_t*)(Ch + (size_t)(rr + 8) * DMODEL + col) =
                pkhf2(scale * (cs[t][2] + bv.x), scale * (cs[t][3] + bv.y));
        }
    }
}

// ===========================================================================
// mma.sync attention — fp16, 128-key stages (2x64 subtiles), 3-stage cp.async,
// Q fragments hoisted to registers, grouped ldsm.
// ===========================================================================

#define OQH 0
#define OST 16384
#define STAGE_SZ 32768          /* K 16KB + V 16KB (128 keys) */
#define SKH 0
#define SVH 16384
#define NSTAGE 3
#define ATTN_SMEM (OST + NSTAGE * STAGE_SZ)   /* 112 KB */
#define NSTG (SEQ / 128)        /* 32 */

__global__ __launch_bounds__(256, 2) void attn_kernel(
    const unsigned short* __restrict__ Qh,
    const unsigned short* __restrict__ Kh,
    const unsigned short* __restrict__ Vh,
    const float* __restrict__ relpos, float* __restrict__ Out)
{
    extern __shared__ char smp[];
    const uint32_t sb = smem_u32(smp);

    const int tid = threadIdx.x;
    const int w = tid >> 5;
    const int lane = tid & 31;
    const int b = blockIdx.z, h = blockIdx.y;
    const int q0 = blockIdx.x * 128;

    const float rb0 = relpos[h * 5 + 0];
    const float rb1 = relpos[h * 5 + 1];
    const float rb2 = relpos[h * 5 + 2];
    const float rb3 = relpos[h * 5 + 3];
    const float rb4 = relpos[h * 5 + 4];

    // ---- Q tile load (128 rows x 128B, SW128) ----
    {
        const int row = tid >> 1;
        const int ch0 = (tid & 1) * 4;
        const size_t gb = (size_t)(b * SEQ + q0 + row) * DMODEL + h * HDIM + ch0 * 8;
#pragma unroll
        for (int ci = 0; ci < 4; ci++) {
            const uint32_t off = SW128((uint32_t)(row * 128 + (ch0 + ci) * 16));
            *(uint4*)(smp + OQH + off) = *(const uint4*)(Qh + gb + ci * 8);
        }
    }

    // ---- K/V stage loader: 128 rows x 128B each; 4 chunks/thread/array ----
    const int krow = tid >> 1;
    const int kch0 = (tid & 1) * 4;
    const size_t kgb0 = (size_t)(b * SEQ + krow) * DMODEL + h * HDIM + kch0 * 8;

    // prologue: stages 0,1
#pragma unroll
    for (int s = 0; s < NSTAGE - 1; s++) {
        const uint32_t st = sb + OST + s * STAGE_SZ;
        const size_t gb = kgb0 + (size_t)(s * 128) * DMODEL;
#pragma unroll
        for (int ci = 0; ci < 4; ci++) {
            const uint32_t off = SW128((uint32_t)(krow * 128 + (kch0 + ci) * 16));
            cpa16(st + SKH + off, Kh + gb + ci * 8);
            cpa16(st + SVH + off, Vh + gb + ci * 8);
        }
        CP_COMMIT();
    }

    const uint32_t base_qa = (uint32_t)((16 * w + (lane & 15)) * 128 + 16 * (lane >> 4));
    const uint32_t base_kb = (uint32_t)(((lane & 7) + ((lane & 16) >> 1)) * 128 + ((lane >> 3) & 1) * 16);
    const uint32_t base_vb = (uint32_t)(((lane & 7) + (lane & 8)) * 128 + ((lane >> 4) & 1) * 16);

    // ---- hoist Q fragments (loop-invariant) ----
    __syncthreads();   // Q stores visible
    uint32_t qa[4][4];
#pragma unroll
    for (int c = 0; c < 4; c++)
        ldsm4(qa[c], sb + OQH + SW128(base_qa + 32u * c));

    float co[8][4];
#pragma unroll
    for (int i = 0; i < 8; i++)
#pragma unroll
        for (int j = 0; j < 4; j++) co[i][j] = 0.f;
    float sum0 = 0.f, sum1 = 0.f;

    const int r0g = q0 + 16 * w + (lane >> 2);
    const int kcol_off = 2 * (lane & 3);

    for (int kt = 0; kt < NSTG; kt++) {
        CP_WAIT1();           // stage kt arrived
        __syncthreads();      // everyone done with buffer being overwritten

        // issue stage kt+2 into buffer (kt+2)%3 (free: computed in iter kt-1)
        if (kt + NSTAGE - 1 < NSTG) {
            const uint32_t st = sb + OST + ((kt + NSTAGE - 1) % NSTAGE) * STAGE_SZ;
            const size_t gb = kgb0 + (size_t)((kt + NSTAGE - 1) * 128) * DMODEL;
#pragma unroll
            for (int ci = 0; ci < 4; ci++) {
                const uint32_t off = SW128((uint32_t)(krow * 128 + (kch0 + ci) * 16));
                cpa16(st + SKH + off, Kh + gb + ci * 8);
                cpa16(st + SVH + off, Vh + gb + ci * 8);
            }
        }
        CP_COMMIT();

        const uint32_t st = sb + OST + (kt % NSTAGE) * STAGE_SZ;

#pragma unroll
        for (int s2 = 0; s2 < 2; s2++) {
            const int k0 = kt * 128 + s2 * 64;
            const uint32_t KHb = st + SKH + s2 * 8192;
            const uint32_t VHb = st + SVH + s2 * 8192;

            // ---- S = Q @ K^T : grouped ldsm, hoisted Q ----
            float cs[8][4];
#pragma unroll
            for (int i = 0; i < 8; i++)
#pragma unroll
                for (int j = 0; j < 4; j++) cs[i][j] = 0.f;

#pragma unroll
            for (int j2 = 0; j2 < 4; j2++) {
                uint32_t bh[4][4];
#pragma unroll
                for (int c = 0; c < 4; c++)
                    ldsm4(bh[c], KHb + SW128(base_kb + 2048u * j2 + 32u * c));
#pragma unroll
                for (int c = 0; c < 4; c++) {
                    mmaf16(cs[2 * j2],     qa[c], bh[c][0], bh[c][1]);
                    mmaf16(cs[2 * j2 + 1], qa[c], bh[c][2], bh[c][3]);
                }
            }

            // ---- bias + exp + rowsum ----
            const bool uni = (k0 - (q0 + 127) > MAXREL) || ((k0 + 63) - q0 < -MAXREL);
            if (uni) {
                const float ub = (k0 > q0) ? rb4 : rb0;
#pragma unroll
                for (int j = 0; j < 8; j++) {
                    cs[j][0] = __expf(cs[j][0] + ub);
                    cs[j][1] = __expf(cs[j][1] + ub);
                    cs[j][2] = __expf(cs[j][2] + ub);
                    cs[j][3] = __expf(cs[j][3] + ub);
                }
            } else {
#pragma unroll
                for (int j = 0; j < 8; j++) {
                    const int kc = k0 + 8 * j + kcol_off;
#pragma unroll
                    for (int i = 0; i < 4; i++) {
                        const int rel = (kc + (i & 1)) - (r0g + (i >> 1) * 8);
                        const float bb = rel <= -MAXREL ? rb0 :
                                         rel >= MAXREL ? rb4 :
                                         rel == -1 ? rb1 : (rel == 0 ? rb2 : rb3);
                        cs[j][i] = __expf(cs[j][i] + bb);
                    }
                }
            }
#pragma unroll
            for (int j = 0; j < 8; j++) {
                sum0 += cs[j][0] + cs[j][1];
                sum1 += cs[j][2] + cs[j][3];
            }

            // ---- O += P @ V : grouped ldsm ----
#pragma unroll
            for (int kc = 0; kc < 4; kc++) {
                uint32_t vh[4][4];
#pragma unroll
                for (int jv = 0; jv < 4; jv++)
                    ldsm4t(vh[jv], VHb + SW128(base_vb + 2048u * kc + 32u * jv));
                uint32_t ph[4];
                ph[0] = pkhf2(cs[2 * kc][0],     cs[2 * kc][1]);
                ph[1] = pkhf2(cs[2 * kc][2],     cs[2 * kc][3]);
                ph[2] = pkhf2(cs[2 * kc + 1][0], cs[2 * kc + 1][1]);
                ph[3] = pkhf2(cs[2 * kc + 1][2], cs[2 * kc + 1][3]);
#pragma unroll
                for (int jv = 0; jv < 4; jv++) {
                    mmaf16(co[2 * jv],     ph, vh[jv][0], vh[jv][1]);
                    mmaf16(co[2 * jv + 1], ph, vh[jv][2], vh[jv][3]);
                }
            }
        }
    }

    sum0 += __shfl_xor_sync(0xFFFFFFFFu, sum0, 1);
    sum0 += __shfl_xor_sync(0xFFFFFFFFu, sum0, 2);
    sum1 += __shfl_xor_sync(0xFFFFFFFFu, sum1, 1);
    sum1 += __shfl_xor_sync(0xFFFFFFFFu, sum1, 2);
    const float inv0 = 1.0f / sum0;
    const float inv1 = 1.0f / sum1;

    {
        float* O0 = Out + (size_t)(b * SEQ + r0g) * DMODEL + h * HDIM + kcol_off;
        float* O1 = O0 + 8 * DMODEL;
#pragma unroll
        for (int j = 0; j < 8; j++) {
            *(float2*)(O0 + 8 * j) = make_float2(co[j][0] * inv0, co[j][1] * inv0);
            *(float2*)(O1 + 8 * j) = make_float2(co[j][2] * inv1, co[j][3] * inv1);
        }
    }
}

// ---------------------------------------------------------------------------
extern "C" void kernel_launch(void* const* d_in, const int* in_sizes, int n_in,
                              void* d_out, int out_size)
{
    const float* q  = (const float*)d_in[0];
    const float* k  = (const float*)d_in[1];
    const float* v  = (const float*)d_in[2];
    const float* Wq = (const float*)d_in[3];
    const float* bq = (const float*)d_in[4];
    const float* Wk = (const float*)d_in[5];
    const float* bk = (const float*)d_in[6];
    const float* Wv = (const float*)d_in[7];
    const float* bv = (const float*)d_in[8];
    const float* Wo = (const float*)d_in[9];
    const float* bo = (const float*)d_in[10];
    const float* rp = (const float*)d_in[11];
    float* out = (float*)d_out;

    float *dA;
    unsigned short *dQh, *dKh, *dVh;
    cudaGetSymbolAddress((void**)&dA, g_A);
    cudaGetSymbolAddress((void**)&dQh, g_Qh);
    cudaGetSymbolAddress((void**)&dKh, g_Kh);
    cudaGetSymbolAddress((void**)&dVh, g_Vh);

    cudaFuncSetAttribute(attn_kernel, cudaFuncAttributeMaxDynamicSharedMemorySize,
                         ATTN_SMEM);

    dim3 gblk(256);
    dim3 ggrid(DMODEL / 128, MROWS / 128);   // (4, 64)

    gemm_bf16<<<ggrid, gblk>>>(q, Wq, bq, nullptr, dQh, 0.125f, 1);
    gemm_bf16<<<ggrid, gblk>>>(k, Wk, bk, nullptr, dKh, 1.0f, 1);
    gemm_bf16<<<ggrid, gblk>>>(v, Wv, bv, nullptr, dVh, 1.0f, 1);

    dim3 agrid(SEQ / 128, NHEAD, BATCH);     // (32, 8, 2)
    attn_kernel<<<agrid, gblk, ATTN_SMEM>>>(dQh, dKh, dVh, rp, dA);

    gemm_bf16<<<ggrid, gblk>>>(dA, Wo, bo, out, nullptr, 1.0f, 0);
}